// round 2
// baseline (speedup 1.0000x reference)
#include <cuda_runtime.h>
#include <cuda_bf16.h>
#include <math.h>

#define NN 50000
#define EE 800000
#define FF 64
#define LL 3
#define GG 50
#define HH 3
#define EPSV 1e-5f

// ---------------- device scratch (statically allocated; no cudaMalloc) --------
__device__ float g_Y[NN * 128];        // [y1 | y2] per node
__device__ float g_aggr[NN * 256];     // [mean|min|max|std]
__device__ float g_Z[NN * 256];
__device__ float g_t[NN * 64];
__device__ float g_xb0[NN * 64];
__device__ float g_xb1[NN * 64];
__device__ int   g_deg[NN];
__device__ int   g_off[NN + 1];
__device__ int   g_cur[NN];
__device__ int   g_ssrc[EE];
__device__ float g_Bcat[LL * 64 * 128];
__device__ float g_b128[LL * 128];
__device__ float g_WcatZ[LL * 256 * 256];
__device__ float g_Wx[LL * 64 * 64];
__device__ float g_bT[LL * 64];
__device__ float g_avg[2];             // [0]=avg_log, [1]=avg_lin
__device__ float g_bnsum[64];
__device__ float g_bnsq[64];
__device__ float g_gsum[GG * 64];
__device__ int   g_gcnt[GG];

__device__ __forceinline__ float* rbuf(int id, const float* ext) {
    switch (id) {
        case 1: return g_Y;
        case 2: return g_aggr;
        case 3: return g_Z;
        case 4: return g_xb0;
        case 5: return g_xb1;
        case 6: return g_Bcat;
        case 7: return g_WcatZ;
        case 8: return g_b128;
        default: return (float*)ext;
    }
}

// ---------------- tiny setup kernels ----------------
__global__ void k_scalars(const float* hist, int nbins) {
    if (threadIdx.x == 0 && blockIdx.x == 0) {
        float tot = 0.f, lin = 0.f, lg = 0.f;
        for (int i = 0; i < nbins; i++) {
            float h = hist[i];
            tot += h;
            lin += (float)i * h;
            lg += logf((float)i + 1.f) * h;
        }
        g_avg[0] = lg / tot;   // avg_log
        g_avg[1] = lin / tot;  // avg_lin
    }
}

__global__ void k_fold_pre(const float* preW, const float* preb) {
    int idx = blockIdx.x * blockDim.x + threadIdx.x;
    int total = LL * 64 * 128;
    if (idx < total) {
        int l = idx / 8192;
        int rem = idx - l * 8192;
        int k = rem >> 7;
        int j = rem & 127;
        float v = (j < 64) ? preW[l * 8192 + k * 64 + j]
                           : preW[l * 8192 + (64 + k) * 64 + (j - 64)];
        g_Bcat[idx] = v;
    }
    if (idx < LL * 128) {
        int l = idx / 128, j = idx % 128;
        g_b128[idx] = (j < 64) ? preb[l * 64 + j] : 0.f;
    }
}

__global__ void k_fold_post(const float* postW, const float* linW,
                            const float* postb, const float* linb) {
    int idx = blockIdx.x * blockDim.x + threadIdx.x;
    int total = LL * 1088 * 64;
    if (idx < total) {
        int l = idx / (1088 * 64);
        int rem = idx - l * 1088 * 64;
        int r = rem >> 6;
        int c = rem & 63;
        const float* pw = postW + (size_t)l * 1088 * 64 + (size_t)r * 64;
        const float* lw = linW + l * 4096;
        float v = 0.f;
        #pragma unroll 16
        for (int m = 0; m < 64; m++) v += pw[m] * lw[m * 64 + c];
        if (r < 64) {
            g_Wx[l * 4096 + r * 64 + c] = v;
        } else {
            int rr = r - 64;
            int k4 = rr >> 8;
            int f = rr & 255;
            g_WcatZ[l * 65536 + f * 256 + k4 * 64 + c] = v;
        }
    }
    if (idx < LL * 64) {
        int l = idx / 64, c = idx % 64;
        float bv = linb[l * 64 + c];
        for (int m = 0; m < 64; m++)
            bv += postb[l * 64 + m] * linW[l * 4096 + m * 64 + c];
        g_bT[idx] = bv;
    }
}

// ---------------- edge sort (counting sort by dst) ----------------
__global__ void k_zero_deg() {
    int i = blockIdx.x * blockDim.x + threadIdx.x;
    if (i < NN) g_deg[i] = 0;
}

__global__ void k_count(const int* dst, int E) {
    int e = blockIdx.x * blockDim.x + threadIdx.x;
    if (e < E) atomicAdd(&g_deg[dst[e]], 1);
}

__global__ void k_scan(int n) {
    __shared__ int wsum[32];
    __shared__ int carry;
    int tid = threadIdx.x, lane = tid & 31, wid = tid >> 5;
    if (tid == 0) carry = 0;
    __syncthreads();
    for (int base = 0; base < n; base += 1024) {
        int i = base + tid;
        int v = (i < n) ? g_deg[i] : 0;
        int x = v;
        #pragma unroll
        for (int o = 1; o < 32; o <<= 1) {
            int y = __shfl_up_sync(0xFFFFFFFFu, x, o);
            if (lane >= o) x += y;
        }
        if (lane == 31) wsum[wid] = x;
        __syncthreads();
        if (wid == 0) {
            int w = wsum[lane];
            #pragma unroll
            for (int o = 1; o < 32; o <<= 1) {
                int y = __shfl_up_sync(0xFFFFFFFFu, w, o);
                if (lane >= o) w += y;
            }
            wsum[lane] = w;
        }
        __syncthreads();
        int incl = x + (wid ? wsum[wid - 1] : 0);
        int total = wsum[31];
        int c = carry;
        __syncthreads();
        int excl = c + incl - v;
        if (i < n) { g_off[i] = excl; g_cur[i] = excl; }
        if (tid == 0) carry = c + total;
        __syncthreads();
    }
    if (threadIdx.x == 0) g_off[n] = carry;
}

__global__ void k_scatter(const int* src, const int* dst, int E) {
    int e = blockIdx.x * blockDim.x + threadIdx.x;
    if (e < E) {
        int p = atomicAdd(&g_cur[dst[e]], 1);
        g_ssrc[p] = src[e];
    }
}

// ---------------- generic fp32 SGEMM: C[M,N] = A[M,K]@B[K,N] (+bias) --------
__global__ void __launch_bounds__(256)
k_gemm(int M, int N, int K,
       int aid, long aoff, int lda, const float* aext,
       int bid, long boff, int ldb,
       int cid, long coff, int ldc,
       int biasid, long biasoff) {
    const float* A = rbuf(aid, aext) + aoff;
    const float* B = rbuf(bid, nullptr) + boff;
    float* C = rbuf(cid, nullptr) + coff;
    const float* bias = biasid ? (rbuf(biasid, nullptr) + biasoff) : nullptr;

    __shared__ float As[8][128];
    __shared__ float Bs[8][128];

    int tid = threadIdx.x;
    int bm = blockIdx.x * 128;
    int bn = blockIdx.y * 128;
    int ty = tid >> 4, tx = tid & 15;
    int arow = tid >> 1;
    int acol4 = (tid & 1) * 4;
    int brow = tid >> 5;
    int bcol4 = (tid & 31) * 4;

    float acc[8][8];
    #pragma unroll
    for (int i = 0; i < 8; i++)
        #pragma unroll
        for (int j = 0; j < 8; j++) acc[i][j] = 0.f;

    for (int k0 = 0; k0 < K; k0 += 8) {
        float4 av = make_float4(0.f, 0.f, 0.f, 0.f);
        int gr = bm + arow;
        if (gr < M) av = *(const float4*)&A[(size_t)gr * lda + k0 + acol4];
        As[acol4 + 0][arow] = av.x;
        As[acol4 + 1][arow] = av.y;
        As[acol4 + 2][arow] = av.z;
        As[acol4 + 3][arow] = av.w;
        float4 bv = *(const float4*)&B[(size_t)(k0 + brow) * ldb + bn + bcol4];
        *(float4*)&Bs[brow][bcol4] = bv;
        __syncthreads();
        #pragma unroll
        for (int k = 0; k < 8; k++) {
            float a[8], b[8];
            *(float4*)(a) = *(const float4*)&As[k][ty * 8];
            *(float4*)(a + 4) = *(const float4*)&As[k][ty * 8 + 4];
            *(float4*)(b) = *(const float4*)&Bs[k][tx * 8];
            *(float4*)(b + 4) = *(const float4*)&Bs[k][tx * 8 + 4];
            #pragma unroll
            for (int i = 0; i < 8; i++)
                #pragma unroll
                for (int j = 0; j < 8; j++) acc[i][j] += a[i] * b[j];
        }
        __syncthreads();
    }

    #pragma unroll
    for (int i = 0; i < 8; i++) {
        int r = bm + ty * 8 + i;
        if (r >= M) continue;
        float* Cr = C + (size_t)r * ldc + bn + tx * 8;
        #pragma unroll
        for (int j = 0; j < 8; j++) {
            float v = acc[i][j];
            if (bias) v += bias[bn + tx * 8 + j];
            Cr[j] = v;
        }
    }
}

// ---------------- PNA aggregation: warp per node ----------------
__global__ void k_aggregate() {
    int w = (blockIdx.x * blockDim.x + threadIdx.x) >> 5;
    if (w >= NN) return;
    int lane = threadIdx.x & 31;
    int beg = g_off[w], end = g_off[w + 1];
    float s0 = 0.f, s1 = 0.f, q0 = 0.f, q1 = 0.f;
    float mn0 = 3.0e38f, mn1 = 3.0e38f, mx0 = -3.0e38f, mx1 = -3.0e38f;
    for (int e = beg; e < end; e++) {
        int sN = g_ssrc[e];
        const float* p = g_Y + (size_t)sN * 128 + 64;
        float v0 = p[lane], v1 = p[lane + 32];
        s0 += v0; q0 += v0 * v0; mn0 = fminf(mn0, v0); mx0 = fmaxf(mx0, v0);
        s1 += v1; q1 += v1 * v1; mn1 = fminf(mn1, v1); mx1 = fmaxf(mx1, v1);
    }
    int cnt = end - beg;
    float degf = (float)(cnt > 0 ? cnt : 1);
    float inv = 1.f / degf;
    float c = (float)cnt;
    const float* yr = g_Y + (size_t)w * 128;
    float y10 = yr[lane], y11 = yr[32 + lane];
    float mean0 = (c * y10 + s0) * inv;
    float mean1 = (c * y11 + s1) * inv;
    float m20 = (c * y10 * y10 + 2.f * y10 * s0 + q0) * inv;
    float m21 = (c * y11 * y11 + 2.f * y11 * s1 + q1) * inv;
    float sd0 = sqrtf(fmaxf(m20 - mean0 * mean0, 0.f) + EPSV);
    float sd1 = sqrtf(fmaxf(m21 - mean1 * mean1, 0.f) + EPSV);
    float MN0 = cnt ? (y10 + mn0) : 0.f;
    float MN1 = cnt ? (y11 + mn1) : 0.f;
    float MX0 = cnt ? (y10 + mx0) : 0.f;
    float MX1 = cnt ? (y11 + mx1) : 0.f;
    float* o = g_aggr + (size_t)w * 256;
    o[lane] = mean0;        o[32 + lane] = mean1;
    o[64 + lane] = MN0;     o[96 + lane] = MN1;
    o[128 + lane] = MX0;    o[160 + lane] = MX1;
    o[192 + lane] = sd0;    o[224 + lane] = sd1;
}

// ---------------- combine: t = x@Wx + Z0 + s1*Z1 + s2*Z2 + s3*Z3 + bT ------
__global__ void __launch_bounds__(256)
k_combine(int l, int xsel, const float* xext) {
    const float* X = (xsel == 0) ? xext : ((xsel == 4) ? g_xb0 : g_xb1);
    const float* Wx = g_Wx + l * 4096;
    const float* bT = g_bT + l * 64;
    __shared__ float xs[64][65];
    __shared__ float ws[64][65];
    int tid = threadIdx.x;
    int base = blockIdx.x * 64;
    for (int i = tid; i < 4096; i += 256) {
        int r = i >> 6, c2 = i & 63;
        ws[r][c2] = Wx[i];
        int gr = base + r;
        xs[r][c2] = (gr < NN) ? X[(size_t)gr * 64 + c2] : 0.f;
    }
    __syncthreads();
    int ty = tid >> 4, tx = tid & 15;
    float acc[4][4];
    #pragma unroll
    for (int i = 0; i < 4; i++)
        #pragma unroll
        for (int j = 0; j < 4; j++) acc[i][j] = 0.f;
    #pragma unroll 8
    for (int k = 0; k < 64; k++) {
        float a[4], b[4];
        #pragma unroll
        for (int i = 0; i < 4; i++) a[i] = xs[ty * 4 + i][k];
        #pragma unroll
        for (int j = 0; j < 4; j++) b[j] = ws[k][tx * 4 + j];
        #pragma unroll
        for (int i = 0; i < 4; i++)
            #pragma unroll
            for (int j = 0; j < 4; j++) acc[i][j] += a[i] * b[j];
    }
    float avgl = g_avg[0], avgn = g_avg[1];
    #pragma unroll
    for (int i = 0; i < 4; i++) {
        int r = base + ty * 4 + i;
        if (r >= NN) continue;
        int cnt = g_deg[r];
        float degf = (float)(cnt > 0 ? cnt : 1);
        float ldg = logf(degf + 1.f);
        float sc1 = ldg / avgl, sc2 = avgl / ldg, sc3 = degf / avgn;
        const float* Zr = g_Z + (size_t)r * 256;
        #pragma unroll
        for (int j = 0; j < 4; j++) {
            int cc = tx * 4 + j;
            float t = acc[i][j] + Zr[cc] + sc1 * Zr[64 + cc] + sc2 * Zr[128 + cc]
                    + sc3 * Zr[192 + cc] + bT[cc];
            g_t[(size_t)r * 64 + cc] = t;
        }
    }
}

// ---------------- BatchNorm (training-mode batch stats) + ReLU ----------------
__global__ void k_zero_bn() {
    int i = threadIdx.x;
    if (i < 64) { g_bnsum[i] = 0.f; g_bnsq[i] = 0.f; }
}

__global__ void __launch_bounds__(256) k_bnstats() {
    const long total = (long)NN * 64;
    long stride = (long)gridDim.x * blockDim.x;  // multiple of 64
    int tid = threadIdx.x;
    float s = 0.f, q = 0.f;
    for (long i = (long)blockIdx.x * blockDim.x + tid; i < total; i += stride) {
        float v = g_t[i];
        s += v; q += v * v;
    }
    __shared__ float ss[256], qq[256];
    ss[tid] = s; qq[tid] = q;
    __syncthreads();
    if (tid < 64) {
        float S = ss[tid] + ss[tid + 64] + ss[tid + 128] + ss[tid + 192];
        float Q = qq[tid] + qq[tid + 64] + qq[tid + 128] + qq[tid + 192];
        atomicAdd(&g_bnsum[tid], S);
        atomicAdd(&g_bnsq[tid], Q);
    }
}

__global__ void __launch_bounds__(256)
k_bnapply(int l, const float* bn_g, const float* bn_b, int outsel) {
    __shared__ float sc[64], sh[64];
    int tid = threadIdx.x;
    if (tid < 64) {
        float m = g_bnsum[tid] / (float)NN;
        float var = g_bnsq[tid] / (float)NN - m * m;
        float gma = bn_g[l * 64 + tid], bet = bn_b[l * 64 + tid];
        float scale = gma * rsqrtf(var + EPSV);
        sc[tid] = scale;
        sh[tid] = bet - m * scale;
    }
    __syncthreads();
    float* out = (outsel == 4) ? g_xb0 : g_xb1;
    long i = (long)blockIdx.x * blockDim.x + tid;
    if (i < (long)NN * 64) {
        int f = (int)(i & 63);
        float v = g_t[i] * sc[f] + sh[f];
        out[i] = fmaxf(v, 0.f);
    }
}

// ---------------- graph pooling + heads ----------------
__global__ void k_zero_pool() {
    int i = blockIdx.x * blockDim.x + threadIdx.x;
    if (i < GG * 64) g_gsum[i] = 0.f;
    if (i < GG) g_gcnt[i] = 0;
}

__global__ void k_pool(const int* batch, int xsel) {
    const float* X = (xsel == 4) ? g_xb0 : g_xb1;
    long i = (long)blockIdx.x * blockDim.x + threadIdx.x;
    if (i < (long)NN * 64) {
        int node = (int)(i >> 6);
        int f = (int)(i & 63);
        atomicAdd(&g_gsum[batch[node] * 64 + f], X[i]);
    }
}

__global__ void k_gcnt(const int* batch) {
    int i = blockIdx.x * blockDim.x + threadIdx.x;
    if (i < NN) atomicAdd(&g_gcnt[batch[i]], 1);
}

__global__ void k_heads(const float* sharedW, const float* sharedb,
                        const float* hW1, const float* hb1,
                        const float* hW2, const float* hb2,
                        const float* hW3, const float* hb3,
                        float* out) {
    __shared__ float gv[64], sv[64], h1[64], h2[32];
    int b = blockIdx.x;
    int tid = threadIdx.x;
    int c = g_gcnt[b];
    float inv = 1.f / (float)(c > 0 ? c : 1);
    gv[tid] = g_gsum[b * 64 + tid] * inv;
    __syncthreads();
    {
        float a = sharedb[tid];
        for (int k = 0; k < 64; k++) a += gv[k] * sharedW[k * 64 + tid];
        sv[tid] = fmaxf(a, 0.f);
    }
    __syncthreads();
    for (int h = 0; h < HH; h++) {
        if (tid < 50) {
            float a = hb1[h * 50 + tid];
            for (int k = 0; k < 64; k++) a += sv[k] * hW1[h * 3200 + k * 50 + tid];
            h1[tid] = fmaxf(a, 0.f);
        }
        __syncthreads();
        if (tid < 25) {
            float a = hb2[h * 25 + tid];
            for (int k = 0; k < 50; k++) a += h1[k] * hW2[h * 1250 + k * 25 + tid];
            h2[tid] = fmaxf(a, 0.f);
        }
        __syncthreads();
        if (tid == 0) {
            float a = hb3[h];
            for (int m = 0; m < 25; m++) a += h2[m] * hW3[h * 25 + m];
            out[b * HH + h] = a;
        }
        __syncthreads();
    }
}

// ---------------- launch ----------------
extern "C" void kernel_launch(void* const* d_in, const int* in_sizes, int n_in,
                              void* d_out, int out_size) {
    const float* x        = (const float*)d_in[0];
    const int*   ei       = (const int*)d_in[1];
    const int*   batch    = (const int*)d_in[2];
    const float* deg_hist = (const float*)d_in[3];
    const float* preW     = (const float*)d_in[4];
    const float* preb     = (const float*)d_in[5];
    const float* postW    = (const float*)d_in[6];
    const float* postb    = (const float*)d_in[7];
    const float* linW     = (const float*)d_in[8];
    const float* linb     = (const float*)d_in[9];
    const float* bn_g     = (const float*)d_in[10];
    const float* bn_b     = (const float*)d_in[11];
    const float* sharedW  = (const float*)d_in[12];
    const float* sharedb  = (const float*)d_in[13];
    const float* hW1      = (const float*)d_in[14];
    const float* hb1      = (const float*)d_in[15];
    const float* hW2      = (const float*)d_in[16];
    const float* hb2      = (const float*)d_in[17];
    const float* hW3      = (const float*)d_in[18];
    const float* hb3      = (const float*)d_in[19];
    float* out = (float*)d_out;

    int E = in_sizes[1] / 2;
    int nbins = in_sizes[3];
    const int* src = ei;
    const int* dst = ei + E;

    // setup / folding
    k_scalars<<<1, 1>>>(deg_hist, nbins);
    k_fold_pre<<<(LL * 64 * 128 + 255) / 256, 256>>>(preW, preb);
    k_fold_post<<<(LL * 1088 * 64 + 255) / 256, 256>>>(postW, linW, postb, linb);

    // counting sort of edges by dst
    k_zero_deg<<<(NN + 255) / 256, 256>>>();
    k_count<<<(E + 255) / 256, 256>>>(dst, E);
    k_scan<<<1, 1024>>>(NN);
    k_scatter<<<(E + 255) / 256, 256>>>(src, dst, E);

    int xsel = 0;
    for (int l = 0; l < LL; l++) {
        // GEMM1: Y[N,128] = x_in @ Bcat + b128
        k_gemm<<<dim3((NN + 127) / 128, 1), 256>>>(
            NN, 128, 64,
            xsel, 0, 64, x,
            6, (long)l * 8192, 128,
            1, 0, 128,
            8, (long)l * 128);
        // PNA aggregation
        k_aggregate<<<(NN * 32 + 255) / 256, 256>>>();
        // GEMM2: Z[N,256] = aggr @ WcatZ[l]
        k_gemm<<<dim3((NN + 127) / 128, 2), 256>>>(
            NN, 256, 256,
            2, 0, 256, nullptr,
            7, (long)l * 65536, 256,
            3, 0, 256,
            0, 0);
        // combine + bias
        k_combine<<<(NN + 63) / 64, 256>>>(l, xsel, x);
        // BN + ReLU
        k_zero_bn<<<1, 64>>>();
        k_bnstats<<<256, 256>>>();
        int outsel = (l % 2 == 0) ? 4 : 5;
        k_bnapply<<<(NN * 64 + 255) / 256, 256>>>(l, bn_g, bn_b, outsel);
        xsel = outsel;
    }

    // pooling + heads
    k_zero_pool<<<(GG * 64 + 255) / 256, 256>>>();
    k_pool<<<(NN * 64 + 255) / 256, 256>>>(batch, xsel);
    k_gcnt<<<(NN + 255) / 256, 256>>>(batch);
    k_heads<<<GG, 64>>>(sharedW, sharedb, hW1, hb1, hW2, hb2, hW3, hb3, out);
}

// round 4
// speedup vs baseline: 1.0749x; 1.0749x over previous
#include <cuda_runtime.h>
#include <cuda_bf16.h>
#include <math.h>

#define NN 50000
#define EE 800000
#define FF 64
#define LL 3
#define GG 50
#define HH 3
#define EPSV 1e-5f

// ---------------- device scratch (statically allocated; no cudaMalloc) --------
__device__ float g_Y[NN * 128];        // [y1 | y2] per node
__device__ float g_aggr[NN * 256];     // [mean|min|max|std]
__device__ float g_Z[NN * 256];
__device__ float g_t[NN * 64];
__device__ float g_xb0[NN * 64];
__device__ float g_xb1[NN * 64];
__device__ int   g_deg[NN];
__device__ int   g_off[NN + 1];
__device__ int   g_cur[NN];
__device__ int   g_ssrc[EE];
__device__ float g_Bcat[LL * 64 * 128];
__device__ float g_b128[LL * 128];
__device__ float g_WcatZ[LL * 256 * 256];
__device__ float g_Wx[LL * 64 * 64];
__device__ float g_bT[LL * 64];
__device__ float g_avg[2];             // [0]=avg_log, [1]=avg_lin
__device__ float g_bnsum[LL * 64];
__device__ float g_bnsq[LL * 64];
__device__ float g_gsum[GG * 64];
__device__ int   g_gcnt[GG];

__device__ __forceinline__ float* rbuf(int id, const float* ext) {
    switch (id) {
        case 1: return g_Y;
        case 2: return g_aggr;
        case 3: return g_Z;
        case 4: return g_xb0;
        case 5: return g_xb1;
        case 6: return g_Bcat;
        case 7: return g_WcatZ;
        case 8: return g_b128;
        default: return (float*)ext;
    }
}

// ---------------- packed f32x2 helpers (Blackwell FFMA2) ----------------
__device__ __forceinline__ unsigned long long pack2(float x, float y) {
    unsigned long long r;
    asm("mov.b64 %0, {%1, %2};" : "=l"(r) : "f"(x), "f"(y));
    return r;
}

// ---------------- tiny setup kernels ----------------
__global__ void k_scalars(const float* hist, int nbins) {
    if (threadIdx.x == 0 && blockIdx.x == 0) {
        float tot = 0.f, lin = 0.f, lg = 0.f;
        for (int i = 0; i < nbins; i++) {
            float h = hist[i];
            tot += h;
            lin += (float)i * h;
            lg += logf((float)i + 1.f) * h;
        }
        g_avg[0] = lg / tot;   // avg_log
        g_avg[1] = lin / tot;  // avg_lin
    }
}

__global__ void k_fold_pre(const float* preW, const float* preb) {
    int idx = blockIdx.x * blockDim.x + threadIdx.x;
    int total = LL * 64 * 128;
    if (idx < total) {
        int l = idx / 8192;
        int rem = idx - l * 8192;
        int k = rem >> 7;
        int j = rem & 127;
        float v = (j < 64) ? preW[l * 8192 + k * 64 + j]
                           : preW[l * 8192 + (64 + k) * 64 + (j - 64)];
        g_Bcat[idx] = v;
    }
    if (idx < LL * 128) {
        int l = idx / 128, j = idx % 128;
        g_b128[idx] = (j < 64) ? preb[l * 64 + j] : 0.f;
    }
}

__global__ void k_fold_post(const float* postW, const float* linW,
                            const float* postb, const float* linb) {
    int idx = blockIdx.x * blockDim.x + threadIdx.x;
    int total = LL * 1088 * 64;
    if (idx < total) {
        int l = idx / (1088 * 64);
        int rem = idx - l * 1088 * 64;
        int r = rem >> 6;
        int c = rem & 63;
        const float* pw = postW + (size_t)l * 1088 * 64 + (size_t)r * 64;
        const float* lw = linW + l * 4096;
        float v = 0.f;
        #pragma unroll 16
        for (int m = 0; m < 64; m++) v += pw[m] * lw[m * 64 + c];
        if (r < 64) {
            g_Wx[l * 4096 + r * 64 + c] = v;
        } else {
            int rr = r - 64;
            int k4 = rr >> 8;
            int f = rr & 255;
            g_WcatZ[l * 65536 + f * 256 + k4 * 64 + c] = v;
        }
    }
    if (idx < LL * 64) {
        int l = idx / 64, c = idx % 64;
        float bv = linb[l * 64 + c];
        for (int m = 0; m < 64; m++)
            bv += postb[l * 64 + m] * linW[l * 4096 + m * 64 + c];
        g_bT[idx] = bv;
    }
}

// ---------------- edge sort (counting sort by dst) ----------------
__global__ void k_zero_deg() {
    int i = blockIdx.x * blockDim.x + threadIdx.x;
    if (i < NN) g_deg[i] = 0;
    if (i < LL * 64) { g_bnsum[i] = 0.f; g_bnsq[i] = 0.f; }
}

__global__ void k_count(const int* dst, int E) {
    int e = blockIdx.x * blockDim.x + threadIdx.x;
    if (e < E) atomicAdd(&g_deg[dst[e]], 1);
}

__global__ void k_scan(int n) {
    __shared__ int wsum[32];
    __shared__ int carry;
    int tid = threadIdx.x, lane = tid & 31, wid = tid >> 5;
    if (tid == 0) carry = 0;
    __syncthreads();
    for (int base = 0; base < n; base += 1024) {
        int i = base + tid;
        int v = (i < n) ? g_deg[i] : 0;
        int x = v;
        #pragma unroll
        for (int o = 1; o < 32; o <<= 1) {
            int y = __shfl_up_sync(0xFFFFFFFFu, x, o);
            if (lane >= o) x += y;
        }
        if (lane == 31) wsum[wid] = x;
        __syncthreads();
        if (wid == 0) {
            int w = wsum[lane];
            #pragma unroll
            for (int o = 1; o < 32; o <<= 1) {
                int y = __shfl_up_sync(0xFFFFFFFFu, w, o);
                if (lane >= o) w += y;
            }
            wsum[lane] = w;
        }
        __syncthreads();
        int incl = x + (wid ? wsum[wid - 1] : 0);
        int total = wsum[31];
        int c = carry;
        __syncthreads();
        int excl = c + incl - v;
        if (i < n) { g_off[i] = excl; g_cur[i] = excl; }
        if (tid == 0) carry = c + total;
        __syncthreads();
    }
    if (threadIdx.x == 0) g_off[n] = carry;
}

__global__ void k_scatter(const int* src, const int* dst, int E) {
    int e = blockIdx.x * blockDim.x + threadIdx.x;
    if (e < E) {
        int p = atomicAdd(&g_cur[dst[e]], 1);
        g_ssrc[p] = src[e];
    }
}

// ---------------- generic scalar fp32 SGEMM (proven path, used for GEMM1) --
__global__ void __launch_bounds__(256)
k_gemm(int M, int N, int K,
       int aid, long aoff, int lda, const float* aext,
       int bid, long boff, int ldb,
       int cid, long coff, int ldc,
       int biasid, long biasoff) {
    const float* A = rbuf(aid, aext) + aoff;
    const float* B = rbuf(bid, nullptr) + boff;
    float* C = rbuf(cid, nullptr) + coff;
    const float* bias = biasid ? (rbuf(biasid, nullptr) + biasoff) : nullptr;

    __shared__ float As[8][128];
    __shared__ float Bs[8][128];

    int tid = threadIdx.x;
    int bm = blockIdx.x * 128;
    int bn = blockIdx.y * 128;
    int ty = tid >> 4, tx = tid & 15;
    int arow = tid >> 1;
    int acol4 = (tid & 1) * 4;
    int brow = tid >> 5;
    int bcol4 = (tid & 31) * 4;

    float acc[8][8];
    #pragma unroll
    for (int i = 0; i < 8; i++)
        #pragma unroll
        for (int j = 0; j < 8; j++) acc[i][j] = 0.f;

    for (int k0 = 0; k0 < K; k0 += 8) {
        float4 av = make_float4(0.f, 0.f, 0.f, 0.f);
        int gr = bm + arow;
        if (gr < M) av = *(const float4*)&A[(size_t)gr * lda + k0 + acol4];
        As[acol4 + 0][arow] = av.x;
        As[acol4 + 1][arow] = av.y;
        As[acol4 + 2][arow] = av.z;
        As[acol4 + 3][arow] = av.w;
        float4 bv = *(const float4*)&B[(size_t)(k0 + brow) * ldb + bn + bcol4];
        *(float4*)&Bs[brow][bcol4] = bv;
        __syncthreads();
        #pragma unroll
        for (int k = 0; k < 8; k++) {
            float a[8], b[8];
            *(float4*)(a) = *(const float4*)&As[k][ty * 8];
            *(float4*)(a + 4) = *(const float4*)&As[k][ty * 8 + 4];
            *(float4*)(b) = *(const float4*)&Bs[k][tx * 8];
            *(float4*)(b + 4) = *(const float4*)&Bs[k][tx * 8 + 4];
            #pragma unroll
            for (int i = 0; i < 8; i++)
                #pragma unroll
                for (int j = 0; j < 8; j++) acc[i][j] += a[i] * b[j];
        }
        __syncthreads();
    }

    #pragma unroll
    for (int i = 0; i < 8; i++) {
        int r = bm + ty * 8 + i;
        if (r >= M) continue;
        float* Cr = C + (size_t)r * ldc + bn + tx * 8;
        #pragma unroll
        for (int j = 0; j < 8; j++) {
            float v = acc[i][j];
            if (bias) v += bias[bn + tx * 8 + j];
            Cr[j] = v;
        }
    }
}

// ------- specialized FFMA2 GEMM2: g_Z[NN,256] = g_aggr[NN,256] @ WcatZ[l] ---
// Accumulators are 32 individually-named 64-bit regs (f32x2 pairs) so nothing
// can be demoted to local memory by the inline asm.
#define FFMA2_OP(d, a, b) \
    asm("fma.rn.f32x2 %0, %1, %2, %0;" : "+l"(d) : "l"(a), "l"(b))

#define DECL_ROW(I) \
    unsigned long long a##I##0 = 0ULL, a##I##1 = 0ULL, \
                       a##I##2 = 0ULL, a##I##3 = 0ULL;

#define FMA_ROW(I, AV) { \
    unsigned long long ap = pack2((AV), (AV)); \
    FFMA2_OP(a##I##0, ap, b0); \
    FFMA2_OP(a##I##1, ap, b1); \
    FFMA2_OP(a##I##2, ap, b2); \
    FFMA2_OP(a##I##3, ap, b3); }

#define STORE_ROW(I) { \
    int r = bm + ty * 8 + I; \
    if (r < NN) { \
        unsigned long long* Cr = \
            (unsigned long long*)(g_Z + (size_t)r * 256 + bn + tx * 8); \
        Cr[0] = a##I##0; Cr[1] = a##I##1; Cr[2] = a##I##2; Cr[3] = a##I##3; } }

__global__ void __launch_bounds__(256) k_gemm2(int l) {
    const float* A = g_aggr;
    const float* B = g_WcatZ + l * 65536;

    __shared__ float As[8][128];
    __shared__ float Bs[8][128];

    int tid = threadIdx.x;
    int bm = blockIdx.x * 128;
    int bn = blockIdx.y * 128;
    int ty = tid >> 4, tx = tid & 15;
    int arow = tid >> 1;
    int acol4 = (tid & 1) * 4;
    int brow = tid >> 5;
    int bcol4 = (tid & 31) * 4;

    DECL_ROW(0) DECL_ROW(1) DECL_ROW(2) DECL_ROW(3)
    DECL_ROW(4) DECL_ROW(5) DECL_ROW(6) DECL_ROW(7)

    for (int k0 = 0; k0 < 256; k0 += 8) {
        float4 av = make_float4(0.f, 0.f, 0.f, 0.f);
        int gr = bm + arow;
        if (gr < NN) av = *(const float4*)&A[(size_t)gr * 256 + k0 + acol4];
        As[acol4 + 0][arow] = av.x;
        As[acol4 + 1][arow] = av.y;
        As[acol4 + 2][arow] = av.z;
        As[acol4 + 3][arow] = av.w;
        float4 bv = *(const float4*)&B[(size_t)(k0 + brow) * 256 + bn + bcol4];
        *(float4*)&Bs[brow][bcol4] = bv;
        __syncthreads();
        #pragma unroll
        for (int k = 0; k < 8; k++) {
            float4 alo = *(const float4*)&As[k][ty * 8];
            float4 ahi = *(const float4*)&As[k][ty * 8 + 4];
            const unsigned long long* bsp =
                (const unsigned long long*)&Bs[k][tx * 8];
            unsigned long long b0 = bsp[0];
            unsigned long long b1 = bsp[1];
            unsigned long long b2 = bsp[2];
            unsigned long long b3 = bsp[3];
            FMA_ROW(0, alo.x) FMA_ROW(1, alo.y)
            FMA_ROW(2, alo.z) FMA_ROW(3, alo.w)
            FMA_ROW(4, ahi.x) FMA_ROW(5, ahi.y)
            FMA_ROW(6, ahi.z) FMA_ROW(7, ahi.w)
        }
        __syncthreads();
    }

    STORE_ROW(0) STORE_ROW(1) STORE_ROW(2) STORE_ROW(3)
    STORE_ROW(4) STORE_ROW(5) STORE_ROW(6) STORE_ROW(7)
}

// ---------------- PNA aggregation: warp per node ----------------
__global__ void k_aggregate() {
    int w = (blockIdx.x * blockDim.x + threadIdx.x) >> 5;
    if (w >= NN) return;
    int lane = threadIdx.x & 31;
    int beg = g_off[w], end = g_off[w + 1];
    float s0 = 0.f, s1 = 0.f, q0 = 0.f, q1 = 0.f;
    float mn0 = 3.0e38f, mn1 = 3.0e38f, mx0 = -3.0e38f, mx1 = -3.0e38f;
    for (int e = beg; e < end; e++) {
        int sN = g_ssrc[e];
        const float* p = g_Y + (size_t)sN * 128 + 64;
        float v0 = p[lane], v1 = p[lane + 32];
        s0 += v0; q0 += v0 * v0; mn0 = fminf(mn0, v0); mx0 = fmaxf(mx0, v0);
        s1 += v1; q1 += v1 * v1; mn1 = fminf(mn1, v1); mx1 = fmaxf(mx1, v1);
    }
    int cnt = end - beg;
    float degf = (float)(cnt > 0 ? cnt : 1);
    float inv = 1.f / degf;
    float c = (float)cnt;
    const float* yr = g_Y + (size_t)w * 128;
    float y10 = yr[lane], y11 = yr[32 + lane];
    float mean0 = (c * y10 + s0) * inv;
    float mean1 = (c * y11 + s1) * inv;
    float m20 = (c * y10 * y10 + 2.f * y10 * s0 + q0) * inv;
    float m21 = (c * y11 * y11 + 2.f * y11 * s1 + q1) * inv;
    float sd0 = sqrtf(fmaxf(m20 - mean0 * mean0, 0.f) + EPSV);
    float sd1 = sqrtf(fmaxf(m21 - mean1 * mean1, 0.f) + EPSV);
    float MN0 = cnt ? (y10 + mn0) : 0.f;
    float MN1 = cnt ? (y11 + mn1) : 0.f;
    float MX0 = cnt ? (y10 + mx0) : 0.f;
    float MX1 = cnt ? (y11 + mx1) : 0.f;
    float* o = g_aggr + (size_t)w * 256;
    o[lane] = mean0;        o[32 + lane] = mean1;
    o[64 + lane] = MN0;     o[96 + lane] = MN1;
    o[128 + lane] = MX0;    o[160 + lane] = MX1;
    o[192 + lane] = sd0;    o[224 + lane] = sd1;
}

// --- combine: t = x@Wx + Z0 + s1*Z1 + s2*Z2 + s3*Z3 + bT, fused BN stats ---
__global__ void __launch_bounds__(256)
k_combine(int l, int xsel, const float* xext) {
    const float* X = (xsel == 0) ? xext : ((xsel == 4) ? g_xb0 : g_xb1);
    const float* Wx = g_Wx + l * 4096;
    const float* bT = g_bT + l * 64;
    __shared__ float xs[64][65];
    __shared__ float ws[64][65];
    __shared__ float ssum[64];
    __shared__ float ssq[64];
    int tid = threadIdx.x;
    int base = blockIdx.x * 64;
    if (tid < 64) { ssum[tid] = 0.f; ssq[tid] = 0.f; }
    for (int i = tid; i < 4096; i += 256) {
        int r = i >> 6, c2 = i & 63;
        ws[r][c2] = Wx[i];
        int gr = base + r;
        xs[r][c2] = (gr < NN) ? X[(size_t)gr * 64 + c2] : 0.f;
    }
    __syncthreads();
    int ty = tid >> 4, tx = tid & 15;
    float acc[4][4];
    #pragma unroll
    for (int i = 0; i < 4; i++)
        #pragma unroll
        for (int j = 0; j < 4; j++) acc[i][j] = 0.f;
    #pragma unroll 8
    for (int k = 0; k < 64; k++) {
        float a[4], b[4];
        #pragma unroll
        for (int i = 0; i < 4; i++) a[i] = xs[ty * 4 + i][k];
        #pragma unroll
        for (int j = 0; j < 4; j++) b[j] = ws[k][tx * 4 + j];
        #pragma unroll
        for (int i = 0; i < 4; i++)
            #pragma unroll
            for (int j = 0; j < 4; j++) acc[i][j] += a[i] * b[j];
    }
    float avgl = g_avg[0], avgn = g_avg[1];
    float ls[4] = {0.f, 0.f, 0.f, 0.f};
    float lq[4] = {0.f, 0.f, 0.f, 0.f};
    #pragma unroll
    for (int i = 0; i < 4; i++) {
        int r = base + ty * 4 + i;
        if (r >= NN) continue;
        int cnt = g_deg[r];
        float degf = (float)(cnt > 0 ? cnt : 1);
        float ldg = logf(degf + 1.f);
        float sc1 = ldg / avgl, sc2 = avgl / ldg, sc3 = degf / avgn;
        const float* Zr = g_Z + (size_t)r * 256;
        #pragma unroll
        for (int j = 0; j < 4; j++) {
            int cc = tx * 4 + j;
            float t = acc[i][j] + Zr[cc] + sc1 * Zr[64 + cc] + sc2 * Zr[128 + cc]
                    + sc3 * Zr[192 + cc] + bT[cc];
            g_t[(size_t)r * 64 + cc] = t;
            ls[j] += t;
            lq[j] += t * t;
        }
    }
    #pragma unroll
    for (int j = 0; j < 4; j++) {
        atomicAdd(&ssum[tx * 4 + j], ls[j]);
        atomicAdd(&ssq[tx * 4 + j], lq[j]);
    }
    __syncthreads();
    if (tid < 64) {
        atomicAdd(&g_bnsum[l * 64 + tid], ssum[tid]);
        atomicAdd(&g_bnsq[l * 64 + tid], ssq[tid]);
    }
}

// ---------------- BatchNorm apply (training-mode batch stats) + ReLU --------
__global__ void __launch_bounds__(256)
k_bnapply(int l, const float* bn_g, const float* bn_b, int outsel) {
    __shared__ float sc[64], sh[64];
    int tid = threadIdx.x;
    if (tid < 64) {
        float m = g_bnsum[l * 64 + tid] / (float)NN;
        float var = g_bnsq[l * 64 + tid] / (float)NN - m * m;
        float gma = bn_g[l * 64 + tid], bet = bn_b[l * 64 + tid];
        float scale = gma * rsqrtf(var + EPSV);
        sc[tid] = scale;
        sh[tid] = bet - m * scale;
    }
    __syncthreads();
    float* out = (outsel == 4) ? g_xb0 : g_xb1;
    long i = (long)blockIdx.x * blockDim.x + tid;
    if (i < (long)NN * 64) {
        int f = (int)(i & 63);
        float v = g_t[i] * sc[f] + sh[f];
        out[i] = fmaxf(v, 0.f);
    }
}

// ---------------- graph pooling + heads ----------------
__global__ void k_zero_pool() {
    int i = blockIdx.x * blockDim.x + threadIdx.x;
    if (i < GG * 64) g_gsum[i] = 0.f;
    if (i < GG) g_gcnt[i] = 0;
}

__global__ void k_pool(const int* batch, int xsel) {
    const float* X = (xsel == 4) ? g_xb0 : g_xb1;
    long i = (long)blockIdx.x * blockDim.x + threadIdx.x;
    if (i < (long)NN * 64) {
        int node = (int)(i >> 6);
        int f = (int)(i & 63);
        atomicAdd(&g_gsum[batch[node] * 64 + f], X[i]);
    }
}

__global__ void k_gcnt(const int* batch) {
    int i = blockIdx.x * blockDim.x + threadIdx.x;
    if (i < NN) atomicAdd(&g_gcnt[batch[i]], 1);
}

__global__ void k_heads(const float* sharedW, const float* sharedb,
                        const float* hW1, const float* hb1,
                        const float* hW2, const float* hb2,
                        const float* hW3, const float* hb3,
                        float* out) {
    __shared__ float gv[64], sv[64], h1[64], h2[32];
    int b = blockIdx.x;
    int tid = threadIdx.x;
    int c = g_gcnt[b];
    float inv = 1.f / (float)(c > 0 ? c : 1);
    gv[tid] = g_gsum[b * 64 + tid] * inv;
    __syncthreads();
    {
        float a = sharedb[tid];
        for (int k = 0; k < 64; k++) a += gv[k] * sharedW[k * 64 + tid];
        sv[tid] = fmaxf(a, 0.f);
    }
    __syncthreads();
    for (int h = 0; h < HH; h++) {
        if (tid < 50) {
            float a = hb1[h * 50 + tid];
            for (int k = 0; k < 64; k++) a += sv[k] * hW1[h * 3200 + k * 50 + tid];
            h1[tid] = fmaxf(a, 0.f);
        }
        __syncthreads();
        if (tid < 25) {
            float a = hb2[h * 25 + tid];
            for (int k = 0; k < 50; k++) a += h1[k] * hW2[h * 1250 + k * 25 + tid];
            h2[tid] = fmaxf(a, 0.f);
        }
        __syncthreads();
        if (tid == 0) {
            float a = hb3[h];
            for (int m = 0; m < 25; m++) a += h2[m] * hW3[h * 25 + m];
            out[b * HH + h] = a;
        }
        __syncthreads();
    }
}

// ---------------- launch ----------------
extern "C" void kernel_launch(void* const* d_in, const int* in_sizes, int n_in,
                              void* d_out, int out_size) {
    const float* x        = (const float*)d_in[0];
    const int*   ei       = (const int*)d_in[1];
    const int*   batch    = (const int*)d_in[2];
    const float* deg_hist = (const float*)d_in[3];
    const float* preW     = (const float*)d_in[4];
    const float* preb     = (const float*)d_in[5];
    const float* postW    = (const float*)d_in[6];
    const float* postb    = (const float*)d_in[7];
    const float* linW     = (const float*)d_in[8];
    const float* linb     = (const float*)d_in[9];
    const float* bn_g     = (const float*)d_in[10];
    const float* bn_b     = (const float*)d_in[11];
    const float* sharedW  = (const float*)d_in[12];
    const float* sharedb  = (const float*)d_in[13];
    const float* hW1      = (const float*)d_in[14];
    const float* hb1      = (const float*)d_in[15];
    const float* hW2      = (const float*)d_in[16];
    const float* hb2      = (const float*)d_in[17];
    const float* hW3      = (const float*)d_in[18];
    const float* hb3      = (const float*)d_in[19];
    float* out = (float*)d_out;

    int E = in_sizes[1] / 2;
    int nbins = in_sizes[3];
    const int* src = ei;
    const int* dst = ei + E;

    // setup / folding
    k_scalars<<<1, 1>>>(deg_hist, nbins);
    k_fold_pre<<<(LL * 64 * 128 + 255) / 256, 256>>>(preW, preb);
    k_fold_post<<<(LL * 1088 * 64 + 255) / 256, 256>>>(postW, linW, postb, linb);

    // counting sort of edges by dst (also zeroes BN accumulators)
    k_zero_deg<<<(NN + 255) / 256, 256>>>();
    k_count<<<(E + 255) / 256, 256>>>(dst, E);
    k_scan<<<1, 1024>>>(NN);
    k_scatter<<<(E + 255) / 256, 256>>>(src, dst, E);

    int xsel = 0;
    for (int l = 0; l < LL; l++) {
        // GEMM1: Y[N,128] = x_in @ Bcat + b128  (proven scalar path)
        k_gemm<<<dim3((NN + 127) / 128, 1), 256>>>(
            NN, 128, 64,
            xsel, 0, 64, x,
            6, (long)l * 8192, 128,
            1, 0, 128,
            8, (long)l * 128);
        // PNA aggregation
        k_aggregate<<<(NN * 32 + 255) / 256, 256>>>();
        // GEMM2: Z[N,256] = aggr @ WcatZ[l]  (FFMA2 path)
        k_gemm2<<<dim3((NN + 127) / 128, 2), 256>>>(l);
        // combine + bias + fused BN stats
        k_combine<<<(NN + 63) / 64, 256>>>(l, xsel, x);
        // BN apply + ReLU
        int outsel = (l % 2 == 0) ? 4 : 5;
        k_bnapply<<<(NN * 64 + 255) / 256, 256>>>(l, bn_g, bn_b, outsel);
        xsel = outsel;
    }

    // pooling + heads
    k_zero_pool<<<(GG * 64 + 255) / 256, 256>>>();
    k_pool<<<(NN * 64 + 255) / 256, 256>>>(batch, xsel);
    k_gcnt<<<(NN + 255) / 256, 256>>>(batch);
    k_heads<<<GG, 64>>>(sharedW, sharedb, hW1, hb1, hW2, hb2, hW3, hb3, out);
}

// round 8
// speedup vs baseline: 1.3427x; 1.2491x over previous
#include <cuda_runtime.h>
#include <cuda_bf16.h>
#include <math.h>

#define NN 50000
#define EE 800000
#define FF 64
#define LL 3
#define GG 50
#define HH 3
#define EPSV 1e-5f

typedef unsigned int uint32;

// ---------------- device scratch (statically allocated; no cudaMalloc) --------
__device__ float g_Y[NN * 128];        // [y1 | y2] per node
__device__ float g_aggr[NN * 256];     // [mean|min|max|std]
__device__ float g_Z[NN * 256];
__device__ float g_t[NN * 64];
__device__ float g_xb0[NN * 64];
__device__ float g_xb1[NN * 64];
__device__ int   g_deg[NN];
__device__ int   g_off[NN + 1];
__device__ int   g_cur[NN];
__device__ int   g_ssrc[EE];
__device__ float g_Bcat[LL * 64 * 128];
__device__ float g_b128[LL * 128];
__device__ float g_WcatZ[LL * 256 * 256];
__device__ __nv_bfloat16 g_Wt_hi[LL * 256 * 256];  // [l][n][k] n-major (col-major B)
__device__ __nv_bfloat16 g_Wt_lo[LL * 256 * 256];
__device__ float g_Wx[LL * 64 * 64];
__device__ float g_bT[LL * 64];
__device__ float g_avg[2];             // [0]=avg_log, [1]=avg_lin
__device__ float g_bnsum[LL * 64];
__device__ float g_bnsq[LL * 64];
__device__ float g_gsum[GG * 64];
__device__ int   g_gcnt[GG];

__device__ __forceinline__ float* rbuf(int id, const float* ext) {
    switch (id) {
        case 1: return g_Y;
        case 2: return g_aggr;
        case 3: return g_Z;
        case 4: return g_xb0;
        case 5: return g_xb1;
        case 6: return g_Bcat;
        case 7: return g_WcatZ;
        case 8: return g_b128;
        default: return (float*)ext;
    }
}

// ---------------- tiny setup kernels ----------------
__global__ void k_scalars(const float* hist, int nbins) {
    if (threadIdx.x == 0 && blockIdx.x == 0) {
        float tot = 0.f, lin = 0.f, lg = 0.f;
        for (int i = 0; i < nbins; i++) {
            float h = hist[i];
            tot += h;
            lin += (float)i * h;
            lg += logf((float)i + 1.f) * h;
        }
        g_avg[0] = lg / tot;   // avg_log
        g_avg[1] = lin / tot;  // avg_lin
    }
}

__global__ void k_fold_pre(const float* preW, const float* preb) {
    int idx = blockIdx.x * blockDim.x + threadIdx.x;
    int total = LL * 64 * 128;
    if (idx < total) {
        int l = idx / 8192;
        int rem = idx - l * 8192;
        int k = rem >> 7;
        int j = rem & 127;
        float v = (j < 64) ? preW[l * 8192 + k * 64 + j]
                           : preW[l * 8192 + (64 + k) * 64 + (j - 64)];
        g_Bcat[idx] = v;
    }
    if (idx < LL * 128) {
        int l = idx / 128, j = idx % 128;
        g_b128[idx] = (j < 64) ? preb[l * 64 + j] : 0.f;
    }
}

__global__ void k_fold_post(const float* postW, const float* linW,
                            const float* postb, const float* linb) {
    int idx = blockIdx.x * blockDim.x + threadIdx.x;
    int total = LL * 1088 * 64;
    if (idx < total) {
        int l = idx / (1088 * 64);
        int rem = idx - l * 1088 * 64;
        int r = rem >> 6;
        int c = rem & 63;
        const float* pw = postW + (size_t)l * 1088 * 64 + (size_t)r * 64;
        const float* lw = linW + l * 4096;
        float v = 0.f;
        #pragma unroll 16
        for (int m = 0; m < 64; m++) v += pw[m] * lw[m * 64 + c];
        if (r < 64) {
            g_Wx[l * 4096 + r * 64 + c] = v;
        } else {
            int rr = r - 64;
            int k4 = rr >> 8;
            int f = rr & 255;
            g_WcatZ[l * 65536 + f * 256 + k4 * 64 + c] = v;
        }
    }
    if (idx < LL * 64) {
        int l = idx / 64, c = idx % 64;
        float bv = linb[l * 64 + c];
        for (int m = 0; m < 64; m++)
            bv += postb[l * 64 + m] * linW[l * 4096 + m * 64 + c];
        g_bT[idx] = bv;
    }
}

// transpose WcatZ[l][f][o] -> Wt[l][o][f], split into bf16 hi/lo
__global__ void k_split_w() {
    int idx = blockIdx.x * blockDim.x + threadIdx.x;
    if (idx >= LL * 256 * 256) return;
    int l = idx >> 16;
    int rem = idx & 65535;
    int o = rem >> 8;       // output col
    int f = rem & 255;      // aggr feature (k dim)
    float w = g_WcatZ[l * 65536 + f * 256 + o];
    __nv_bfloat16 hi = __float2bfloat16(w);
    __nv_bfloat16 lo = __float2bfloat16(w - __bfloat162float(hi));
    g_Wt_hi[l * 65536 + o * 256 + f] = hi;
    g_Wt_lo[l * 65536 + o * 256 + f] = lo;
}

// ---------------- edge sort (counting sort by dst) ----------------
__global__ void k_zero_deg() {
    int i = blockIdx.x * blockDim.x + threadIdx.x;
    if (i < NN) g_deg[i] = 0;
    if (i < LL * 64) { g_bnsum[i] = 0.f; g_bnsq[i] = 0.f; }
}

__global__ void k_count(const int* dst, int E) {
    int e = blockIdx.x * blockDim.x + threadIdx.x;
    if (e < E) atomicAdd(&g_deg[dst[e]], 1);
}

__global__ void k_scan(int n) {
    __shared__ int wsum[32];
    __shared__ int carry;
    int tid = threadIdx.x, lane = tid & 31, wid = tid >> 5;
    if (tid == 0) carry = 0;
    __syncthreads();
    for (int base = 0; base < n; base += 1024) {
        int i = base + tid;
        int v = (i < n) ? g_deg[i] : 0;
        int x = v;
        #pragma unroll
        for (int o = 1; o < 32; o <<= 1) {
            int y = __shfl_up_sync(0xFFFFFFFFu, x, o);
            if (lane >= o) x += y;
        }
        if (lane == 31) wsum[wid] = x;
        __syncthreads();
        if (wid == 0) {
            int w = wsum[lane];
            #pragma unroll
            for (int o = 1; o < 32; o <<= 1) {
                int y = __shfl_up_sync(0xFFFFFFFFu, w, o);
                if (lane >= o) w += y;
            }
            wsum[lane] = w;
        }
        __syncthreads();
        int incl = x + (wid ? wsum[wid - 1] : 0);
        int total = wsum[31];
        int c = carry;
        __syncthreads();
        int excl = c + incl - v;
        if (i < n) { g_off[i] = excl; g_cur[i] = excl; }
        if (tid == 0) carry = c + total;
        __syncthreads();
    }
    if (threadIdx.x == 0) g_off[n] = carry;
}

__global__ void k_scatter(const int* src, const int* dst, int E) {
    int e = blockIdx.x * blockDim.x + threadIdx.x;
    if (e < E) {
        int p = atomicAdd(&g_cur[dst[e]], 1);
        g_ssrc[p] = src[e];
    }
}

// ---------------- generic scalar fp32 SGEMM (used for GEMM1) ----------------
__global__ void __launch_bounds__(256)
k_gemm(int M, int N, int K,
       int aid, long aoff, int lda, const float* aext,
       int bid, long boff, int ldb,
       int cid, long coff, int ldc,
       int biasid, long biasoff) {
    const float* A = rbuf(aid, aext) + aoff;
    const float* B = rbuf(bid, nullptr) + boff;
    float* C = rbuf(cid, nullptr) + coff;
    const float* bias = biasid ? (rbuf(biasid, nullptr) + biasoff) : nullptr;

    __shared__ float As[8][128];
    __shared__ float Bs[8][128];

    int tid = threadIdx.x;
    int bm = blockIdx.x * 128;
    int bn = blockIdx.y * 128;
    int ty = tid >> 4, tx = tid & 15;
    int arow = tid >> 1;
    int acol4 = (tid & 1) * 4;
    int brow = tid >> 5;
    int bcol4 = (tid & 31) * 4;

    float acc[8][8];
    #pragma unroll
    for (int i = 0; i < 8; i++)
        #pragma unroll
        for (int j = 0; j < 8; j++) acc[i][j] = 0.f;

    for (int k0 = 0; k0 < K; k0 += 8) {
        float4 av = make_float4(0.f, 0.f, 0.f, 0.f);
        int gr = bm + arow;
        if (gr < M) av = *(const float4*)&A[(size_t)gr * lda + k0 + acol4];
        As[acol4 + 0][arow] = av.x;
        As[acol4 + 1][arow] = av.y;
        As[acol4 + 2][arow] = av.z;
        As[acol4 + 3][arow] = av.w;
        float4 bv = *(const float4*)&B[(size_t)(k0 + brow) * ldb + bn + bcol4];
        *(float4*)&Bs[brow][bcol4] = bv;
        __syncthreads();
        #pragma unroll
        for (int k = 0; k < 8; k++) {
            float a[8], b[8];
            *(float4*)(a) = *(const float4*)&As[k][ty * 8];
            *(float4*)(a + 4) = *(const float4*)&As[k][ty * 8 + 4];
            *(float4*)(b) = *(const float4*)&Bs[k][tx * 8];
            *(float4*)(b + 4) = *(const float4*)&Bs[k][tx * 8 + 4];
            #pragma unroll
            for (int i = 0; i < 8; i++)
                #pragma unroll
                for (int j = 0; j < 8; j++) acc[i][j] += a[i] * b[j];
        }
        __syncthreads();
    }

    #pragma unroll
    for (int i = 0; i < 8; i++) {
        int r = bm + ty * 8 + i;
        if (r >= M) continue;
        float* Cr = C + (size_t)r * ldc + bn + tx * 8;
        #pragma unroll
        for (int j = 0; j < 8; j++) {
            float v = acc[i][j];
            if (bias) v += bias[bn + tx * 8 + j];
            Cr[j] = v;
        }
    }
}

// -------- tensor-core GEMM2: Z[NN,256] = aggr[NN,256] @ WcatZ[l] ------------
// mma.sync.m16n8k16 bf16, error-compensated split: AhBh + AlBh + AhBl.
__device__ __forceinline__ void mma16816(float* c, const uint32* a,
                                         uint32 b0, uint32 b1) {
    asm volatile(
        "mma.sync.aligned.m16n8k16.row.col.f32.bf16.bf16.f32 "
        "{%0,%1,%2,%3},{%4,%5,%6,%7},{%8,%9},{%0,%1,%2,%3};"
        : "+f"(c[0]), "+f"(c[1]), "+f"(c[2]), "+f"(c[3])
        : "r"(a[0]), "r"(a[1]), "r"(a[2]), "r"(a[3]), "r"(b0), "r"(b1));
}

#define KCH 32          // k-chunk
#define SPAD 40         // padded smem row stride (bf16 elems) -> conflict-free

__global__ void __launch_bounds__(256) k_gemm2_mma(int l) {
    __shared__ __nv_bfloat16 Ah[128][SPAD];
    __shared__ __nv_bfloat16 Al[128][SPAD];
    __shared__ __nv_bfloat16 Bh[128][SPAD];
    __shared__ __nv_bfloat16 Bl[128][SPAD];

    int tid = threadIdx.x;
    int lane = tid & 31;
    int warp = tid >> 5;
    int bm = blockIdx.x * 128;
    int bn = blockIdx.y * 128;
    int wm = (warp & 3) * 32;   // 2 m-frags of 16
    int wn = (warp >> 2) * 64;  // 8 n-frags of 8

    const __nv_bfloat16* WH = g_Wt_hi + l * 65536;
    const __nv_bfloat16* WL = g_Wt_lo + l * 65536;

    float acc[2][8][4];
    #pragma unroll
    for (int f = 0; f < 2; f++)
        #pragma unroll
        for (int j = 0; j < 8; j++)
            #pragma unroll
            for (int q = 0; q < 4; q++) acc[f][j][q] = 0.f;

    int ar = lane >> 2;
    int ac2 = (lane & 3) * 2;

    for (int k0 = 0; k0 < 256; k0 += KCH) {
        // ---- load A tile [128, KCH] fp32 -> split bf16 hi/lo ----
        #pragma unroll
        for (int i = 0; i < 4; i++) {
            int id = tid + i * 256;           // 0..1023 float4 slots
            int row = id >> 3;
            int c4 = (id & 7) * 4;
            float4 v = make_float4(0.f, 0.f, 0.f, 0.f);
            if (bm + row < NN)
                v = *(const float4*)&g_aggr[(size_t)(bm + row) * 256 + k0 + c4];
            float vv[4] = {v.x, v.y, v.z, v.w};
            #pragma unroll
            for (int q = 0; q < 4; q++) {
                __nv_bfloat16 h = __float2bfloat16(vv[q]);
                Ah[row][c4 + q] = h;
                Al[row][c4 + q] = __float2bfloat16(vv[q] - __bfloat162float(h));
            }
        }
        // ---- load B tiles (pre-split bf16, n-major) ----
        #pragma unroll
        for (int i = 0; i < 8; i++) {
            int id = tid + i * 256;           // 0..2047 uint slots
            int row = id >> 4;
            int cu = (id & 15) * 2;
            uint32 uh = *(const uint32*)&WH[(size_t)(bn + row) * 256 + k0 + cu];
            uint32 ul = *(const uint32*)&WL[(size_t)(bn + row) * 256 + k0 + cu];
            *(uint32*)&Bh[row][cu] = uh;
            *(uint32*)&Bl[row][cu] = ul;
        }
        __syncthreads();

        #pragma unroll
        for (int kk = 0; kk < KCH; kk += 16) {
            uint32 ah[2][4], al[2][4];
            #pragma unroll
            for (int f = 0; f < 2; f++) {
                int r = wm + f * 16;
                ah[f][0] = *(const uint32*)&Ah[r + ar][kk + ac2];
                ah[f][1] = *(const uint32*)&Ah[r + ar + 8][kk + ac2];
                ah[f][2] = *(const uint32*)&Ah[r + ar][kk + ac2 + 8];
                ah[f][3] = *(const uint32*)&Ah[r + ar + 8][kk + ac2 + 8];
                al[f][0] = *(const uint32*)&Al[r + ar][kk + ac2];
                al[f][1] = *(const uint32*)&Al[r + ar + 8][kk + ac2];
                al[f][2] = *(const uint32*)&Al[r + ar][kk + ac2 + 8];
                al[f][3] = *(const uint32*)&Al[r + ar + 8][kk + ac2 + 8];
            }
            #pragma unroll
            for (int j = 0; j < 8; j++) {
                int n = wn + j * 8 + ar;
                int kb = kk + ac2;
                uint32 bh0 = *(const uint32*)&Bh[n][kb];
                uint32 bh1 = *(const uint32*)&Bh[n][kb + 8];
                uint32 bl0 = *(const uint32*)&Bl[n][kb];
                uint32 bl1 = *(const uint32*)&Bl[n][kb + 8];
                #pragma unroll
                for (int f = 0; f < 2; f++) {
                    mma16816(acc[f][j], ah[f], bh0, bh1);
                    mma16816(acc[f][j], al[f], bh0, bh1);
                    mma16816(acc[f][j], ah[f], bl0, bl1);
                }
            }
        }
        __syncthreads();
    }

    // ---- epilogue: write Z ----
    #pragma unroll
    for (int f = 0; f < 2; f++) {
        int r0 = bm + wm + f * 16 + ar;
        #pragma unroll
        for (int j = 0; j < 8; j++) {
            int cc = bn + wn + j * 8 + ac2;
            if (r0 < NN) {
                g_Z[(size_t)r0 * 256 + cc] = acc[f][j][0];
                g_Z[(size_t)r0 * 256 + cc + 1] = acc[f][j][1];
            }
            if (r0 + 8 < NN) {
                g_Z[(size_t)(r0 + 8) * 256 + cc] = acc[f][j][2];
                g_Z[(size_t)(r0 + 8) * 256 + cc + 1] = acc[f][j][3];
            }
        }
    }
}

// ---------------- PNA aggregation: warp per node ----------------
__global__ void k_aggregate() {
    int w = (blockIdx.x * blockDim.x + threadIdx.x) >> 5;
    if (w >= NN) return;
    int lane = threadIdx.x & 31;
    int beg = g_off[w], end = g_off[w + 1];
    float s0 = 0.f, s1 = 0.f, q0 = 0.f, q1 = 0.f;
    float mn0 = 3.0e38f, mn1 = 3.0e38f, mx0 = -3.0e38f, mx1 = -3.0e38f;
    for (int e = beg; e < end; e++) {
        int sN = g_ssrc[e];
        const float* p = g_Y + (size_t)sN * 128 + 64;
        float v0 = p[lane], v1 = p[lane + 32];
        s0 += v0; q0 += v0 * v0; mn0 = fminf(mn0, v0); mx0 = fmaxf(mx0, v0);
        s1 += v1; q1 += v1 * v1; mn1 = fminf(mn1, v1); mx1 = fmaxf(mx1, v1);
    }
    int cnt = end - beg;
    float degf = (float)(cnt > 0 ? cnt : 1);
    float inv = 1.f / degf;
    float c = (float)cnt;
    const float* yr = g_Y + (size_t)w * 128;
    float y10 = yr[lane], y11 = yr[32 + lane];
    float mean0 = (c * y10 + s0) * inv;
    float mean1 = (c * y11 + s1) * inv;
    float m20 = (c * y10 * y10 + 2.f * y10 * s0 + q0) * inv;
    float m21 = (c * y11 * y11 + 2.f * y11 * s1 + q1) * inv;
    float sd0 = sqrtf(fmaxf(m20 - mean0 * mean0, 0.f) + EPSV);
    float sd1 = sqrtf(fmaxf(m21 - mean1 * mean1, 0.f) + EPSV);
    float MN0 = cnt ? (y10 + mn0) : 0.f;
    float MN1 = cnt ? (y11 + mn1) : 0.f;
    float MX0 = cnt ? (y10 + mx0) : 0.f;
    float MX1 = cnt ? (y11 + mx1) : 0.f;
    float* o = g_aggr + (size_t)w * 256;
    o[lane] = mean0;        o[32 + lane] = mean1;
    o[64 + lane] = MN0;     o[96 + lane] = MN1;
    o[128 + lane] = MX0;    o[160 + lane] = MX1;
    o[192 + lane] = sd0;    o[224 + lane] = sd1;
}

// --- combine: t = x@Wx + Z0 + s1*Z1 + s2*Z2 + s3*Z3 + bT, fused BN stats ---
__global__ void __launch_bounds__(256)
k_combine(int l, int xsel, const float* xext) {
    const float* X = (xsel == 0) ? xext : ((xsel == 4) ? g_xb0 : g_xb1);
    const float* Wx = g_Wx + l * 4096;
    const float* bT = g_bT + l * 64;
    __shared__ float xs[64][65];
    __shared__ float ws[64][65];
    __shared__ float ssum[64];
    __shared__ float ssq[64];
    int tid = threadIdx.x;
    int base = blockIdx.x * 64;
    if (tid < 64) { ssum[tid] = 0.f; ssq[tid] = 0.f; }
    for (int i = tid; i < 4096; i += 256) {
        int r = i >> 6, c2 = i & 63;
        ws[r][c2] = Wx[i];
        int gr = base + r;
        xs[r][c2] = (gr < NN) ? X[(size_t)gr * 64 + c2] : 0.f;
    }
    __syncthreads();
    int ty = tid >> 4, tx = tid & 15;
    float acc[4][4];
    #pragma unroll
    for (int i = 0; i < 4; i++)
        #pragma unroll
        for (int j = 0; j < 4; j++) acc[i][j] = 0.f;
    #pragma unroll 8
    for (int k = 0; k < 64; k++) {
        float a[4], b[4];
        #pragma unroll
        for (int i = 0; i < 4; i++) a[i] = xs[ty * 4 + i][k];
        #pragma unroll
        for (int j = 0; j < 4; j++) b[j] = ws[k][tx * 4 + j];
        #pragma unroll
        for (int i = 0; i < 4; i++)
            #pragma unroll
            for (int j = 0; j < 4; j++) acc[i][j] += a[i] * b[j];
    }
    float avgl = g_avg[0], avgn = g_avg[1];
    float ls[4] = {0.f, 0.f, 0.f, 0.f};
    float lq[4] = {0.f, 0.f, 0.f, 0.f};
    #pragma unroll
    for (int i = 0; i < 4; i++) {
        int r = base + ty * 4 + i;
        if (r >= NN) continue;
        int cnt = g_deg[r];
        float degf = (float)(cnt > 0 ? cnt : 1);
        float ldg = logf(degf + 1.f);
        float sc1 = ldg / avgl, sc2 = avgl / ldg, sc3 = degf / avgn;
        const float* Zr = g_Z + (size_t)r * 256;
        #pragma unroll
        for (int j = 0; j < 4; j++) {
            int cc = tx * 4 + j;
            float t = acc[i][j] + Zr[cc] + sc1 * Zr[64 + cc] + sc2 * Zr[128 + cc]
                    + sc3 * Zr[192 + cc] + bT[cc];
            g_t[(size_t)r * 64 + cc] = t;
            ls[j] += t;
            lq[j] += t * t;
        }
    }
    #pragma unroll
    for (int j = 0; j < 4; j++) {
        atomicAdd(&ssum[tx * 4 + j], ls[j]);
        atomicAdd(&ssq[tx * 4 + j], lq[j]);
    }
    __syncthreads();
    if (tid < 64) {
        atomicAdd(&g_bnsum[l * 64 + tid], ssum[tid]);
        atomicAdd(&g_bnsq[l * 64 + tid], ssq[tid]);
    }
}

// ---------------- BatchNorm apply (training-mode batch stats) + ReLU --------
__global__ void __launch_bounds__(256)
k_bnapply(int l, const float* bn_g, const float* bn_b, int outsel) {
    __shared__ float sc[64], sh[64];
    int tid = threadIdx.x;
    if (tid < 64) {
        float m = g_bnsum[l * 64 + tid] / (float)NN;
        float var = g_bnsq[l * 64 + tid] / (float)NN - m * m;
        float gma = bn_g[l * 64 + tid], bet = bn_b[l * 64 + tid];
        float scale = gma * rsqrtf(var + EPSV);
        sc[tid] = scale;
        sh[tid] = bet - m * scale;
    }
    __syncthreads();
    float* out = (outsel == 4) ? g_xb0 : g_xb1;
    long i = (long)blockIdx.x * blockDim.x + tid;
    if (i < (long)NN * 64) {
        int f = (int)(i & 63);
        float v = g_t[i] * sc[f] + sh[f];
        out[i] = fmaxf(v, 0.f);
    }
}

// ---------------- graph pooling + heads ----------------
__global__ void k_zero_pool() {
    int i = blockIdx.x * blockDim.x + threadIdx.x;
    if (i < GG * 64) g_gsum[i] = 0.f;
    if (i < GG) g_gcnt[i] = 0;
}

__global__ void k_pool(const int* batch, int xsel) {
    const float* X = (xsel == 4) ? g_xb0 : g_xb1;
    long i = (long)blockIdx.x * blockDim.x + threadIdx.x;
    if (i < (long)NN * 64) {
        int node = (int)(i >> 6);
        int f = (int)(i & 63);
        atomicAdd(&g_gsum[batch[node] * 64 + f], X[i]);
    }
}

__global__ void k_gcnt(const int* batch) {
    int i = blockIdx.x * blockDim.x + threadIdx.x;
    if (i < NN) atomicAdd(&g_gcnt[batch[i]], 1);
}

__global__ void k_heads(const float* sharedW, const float* sharedb,
                        const float* hW1, const float* hb1,
                        const float* hW2, const float* hb2,
                        const float* hW3, const float* hb3,
                        float* out) {
    __shared__ float gv[64], sv[64], h1[64], h2[32];
    int b = blockIdx.x;
    int tid = threadIdx.x;
    int c = g_gcnt[b];
    float inv = 1.f / (float)(c > 0 ? c : 1);
    gv[tid] = g_gsum[b * 64 + tid] * inv;
    __syncthreads();
    {
        float a = sharedb[tid];
        for (int k = 0; k < 64; k++) a += gv[k] * sharedW[k * 64 + tid];
        sv[tid] = fmaxf(a, 0.f);
    }
    __syncthreads();
    for (int h = 0; h < HH; h++) {
        if (tid < 50) {
            float a = hb1[h * 50 + tid];
            for (int k = 0; k < 64; k++) a += sv[k] * hW1[h * 3200 + k * 50 + tid];
            h1[tid] = fmaxf(a, 0.f);
        }
        __syncthreads();
        if (tid < 25) {
            float a = hb2[h * 25 + tid];
            for (int k = 0; k < 50; k++) a += h1[k] * hW2[h * 1250 + k * 25 + tid];
            h2[tid] = fmaxf(a, 0.f);
        }
        __syncthreads();
        if (tid == 0) {
            float a = hb3[h];
            for (int m = 0; m < 25; m++) a += h2[m] * hW3[h * 25 + m];
            out[b * HH + h] = a;
        }
        __syncthreads();
    }
}

// ---------------- launch ----------------
extern "C" void kernel_launch(void* const* d_in, const int* in_sizes, int n_in,
                              void* d_out, int out_size) {
    const float* x        = (const float*)d_in[0];
    const int*   ei       = (const int*)d_in[1];
    const int*   batch    = (const int*)d_in[2];
    const float* deg_hist = (const float*)d_in[3];
    const float* preW     = (const float*)d_in[4];
    const float* preb     = (const float*)d_in[5];
    const float* postW    = (const float*)d_in[6];
    const float* postb    = (const float*)d_in[7];
    const float* linW     = (const float*)d_in[8];
    const float* linb     = (const float*)d_in[9];
    const float* bn_g     = (const float*)d_in[10];
    const float* bn_b     = (const float*)d_in[11];
    const float* sharedW  = (const float*)d_in[12];
    const float* sharedb  = (const float*)d_in[13];
    const float* hW1      = (const float*)d_in[14];
    const float* hb1      = (const float*)d_in[15];
    const float* hW2      = (const float*)d_in[16];
    const float* hb2      = (const float*)d_in[17];
    const float* hW3      = (const float*)d_in[18];
    const float* hb3      = (const float*)d_in[19];
    float* out = (float*)d_out;

    int E = in_sizes[1] / 2;
    int nbins = in_sizes[3];
    const int* src = ei;
    const int* dst = ei + E;

    // setup / folding
    k_scalars<<<1, 1>>>(deg_hist, nbins);
    k_fold_pre<<<(LL * 64 * 128 + 255) / 256, 256>>>(preW, preb);
    k_fold_post<<<(LL * 1088 * 64 + 255) / 256, 256>>>(postW, linW, postb, linb);
    k_split_w<<<(LL * 256 * 256 + 255) / 256, 256>>>();

    // counting sort of edges by dst (also zeroes BN accumulators)
    k_zero_deg<<<(NN + 255) / 256, 256>>>();
    k_count<<<(E + 255) / 256, 256>>>(dst, E);
    k_scan<<<1, 1024>>>(NN);
    k_scatter<<<(E + 255) / 256, 256>>>(src, dst, E);

    int xsel = 0;
    for (int l = 0; l < LL; l++) {
        // GEMM1: Y[N,128] = x_in @ Bcat + b128  (scalar path)
        k_gemm<<<dim3((NN + 127) / 128, 1), 256>>>(
            NN, 128, 64,
            xsel, 0, 64, x,
            6, (long)l * 8192, 128,
            1, 0, 128,
            8, (long)l * 128);
        // PNA aggregation
        k_aggregate<<<(NN * 32 + 255) / 256, 256>>>();
        // GEMM2: Z[N,256] = aggr @ WcatZ[l]  (tensor-core, error-compensated)
        k_gemm2_mma<<<dim3((NN + 127) / 128, 2), 256>>>(l);
        // combine + bias + fused BN stats
        k_combine<<<(NN + 63) / 64, 256>>>(l, xsel, x);
        // BN apply + ReLU
        int outsel = (l % 2 == 0) ? 4 : 5;
        k_bnapply<<<(NN * 64 + 255) / 256, 256>>>(l, bn_g, bn_b, outsel);
        xsel = outsel;
    }

    // pooling + heads
    k_zero_pool<<<(GG * 64 + 255) / 256, 256>>>();
    k_pool<<<(NN * 64 + 255) / 256, 256>>>(batch, xsel);
    k_gcnt<<<(NN + 255) / 256, 256>>>(batch);
    k_heads<<<GG, 64>>>(sharedW, sharedb, hW1, hb1, hW2, hb2, hW3, hb3, out);
}